// round 14
// baseline (speedup 1.0000x reference)
#include <cuda_runtime.h>
#include <cuda_fp16.h>
#include <cstdint>
#include <cstddef>

#define N_NODES 50000
#define N_EDGES 800000
#define FEAT    128
#define HEADS   8
#define NEG_SLOPE 0.2f
#define NT2     12500       // 64-edge tiles
#define GRID_P4 592         // persistent CTAs (4 per SM)

typedef unsigned long long u64;
typedef unsigned int u32;

// ---------------- device scratch ---------------------------------------------
__device__ __half g_feat_src[(size_t)N_NODES * FEAT];   // 12.8 MB (fp16)
__device__ __half g_feat_dst[(size_t)N_NODES * FEAT];   // 12.8 MB (fp16)
__device__ float g_z[(size_t)N_NODES * HEADS];
__device__ __half g_wh[3 * FEAT * FEAT];                // fp16 weights (hi only)

// ---------------- smem maps ---------------------------------------------------
#define PAD2    136
// node kernel (256 thr, 2 CTA/SM): A tile + W tile + D overlay on W
#define SA_N    0
#define SW_N    34816
#define SD_N    34816           // f32 D overlays W (34816+67584 <= SMEM_N)
#define SMEM_N  104448
// edge kernel (256 thr, 4 CTA/SM): A/D overlay (64 x 136 fp16) + W fp16
#define SAD_E   0               // A during MMA, then D (fp16) after
#define SW_E    17408           // 128 x 136 fp16 = 34816
#define SMEM_E  52224

// ---------------- helpers -----------------------------------------------------
__device__ __forceinline__ u32 smem_u32(const void* p) {
    u32 a;
    asm("{ .reg .u64 t; cvta.to.shared.u64 t, %1; cvt.u32.u64 %0, t; }"
        : "=r"(a) : "l"(p));
    return a;
}
__device__ __forceinline__ void ldsm4(u32& r0, u32& r1, u32& r2, u32& r3, u32 addr) {
    asm volatile("ldmatrix.sync.aligned.m8n8.x4.shared.b16 {%0,%1,%2,%3}, [%4];"
                 : "=r"(r0), "=r"(r1), "=r"(r2), "=r"(r3) : "r"(addr));
}
__device__ __forceinline__ void mma_f16(float* c, const u32* a, u32 b0, u32 b1) {
    asm volatile("mma.sync.aligned.m16n8k16.row.col.f32.f16.f16.f32 "
                 "{%0,%1,%2,%3}, {%4,%5,%6,%7}, {%8,%9}, {%0,%1,%2,%3};"
                 : "+f"(c[0]), "+f"(c[1]), "+f"(c[2]), "+f"(c[3])
                 : "r"(a[0]), "r"(a[1]), "r"(a[2]), "r"(a[3]), "r"(b0), "r"(b1));
}
__device__ __forceinline__ u64 cvt4_f16(float4 v) {
    u32 p01, p23;
    asm("cvt.rn.f16x2.f32 %0, %1, %2;" : "=r"(p01) : "f"(v.y), "f"(v.x));
    asm("cvt.rn.f16x2.f32 %0, %1, %2;" : "=r"(p23) : "f"(v.w), "f"(v.z));
    return (u64)p01 | ((u64)p23 << 32);
}
__device__ __forceinline__ u32 cvt2_f16(float a, float b) {
    u32 r;
    asm("cvt.rn.f16x2.f32 %0, %1, %2;" : "=r"(r) : "f"(b), "f"(a));
    return r;
}
__device__ __forceinline__ void cp_async16(u32 saddr, const void* gaddr) {
    asm volatile("cp.async.cg.shared.global [%0], [%1], 16;"
                 :: "r"(saddr), "l"(gaddr) : "memory");
}
__device__ __forceinline__ void cp_async_wait_all() {
    asm volatile("cp.async.commit_group;" ::: "memory");
    asm volatile("cp.async.wait_group 0;" ::: "memory");
}
__device__ __forceinline__ float4 h4_to_f4(uint2 hv) {
    __half2 h01 = *reinterpret_cast<__half2*>(&hv.x);
    __half2 h23 = *reinterpret_cast<__half2*>(&hv.y);
    float2 f01 = __half22float2(h01);
    float2 f23 = __half22float2(h23);
    return make_float4(f01.x, f01.y, f23.x, f23.y);
}
__device__ __forceinline__ float4 gather_h4(const __half* base, int node, int lane) {
    uint2 hv = *(const uint2*)(base + (size_t)node * FEAT + lane * 4);
    return h4_to_f4(hv);
}
__device__ __forceinline__ float4 ldcs4(const float* p) {
    float4 v;
    asm("ld.global.cs.v4.f32 {%0,%1,%2,%3}, [%4];"
        : "=f"(v.x), "=f"(v.y), "=f"(v.z), "=f"(v.w) : "l"(p));
    return v;
}

// ---------------- K0: zero ----------------------------------------------------
__global__ void zero_kernel(float4* __restrict__ out4)
{
    int i = blockIdx.x * blockDim.x + threadIdx.x;
    if (i < N_NODES * 32) out4[i] = make_float4(0.f, 0.f, 0.f, 0.f);
    if (i < N_NODES * HEADS / 4) ((float4*)g_z)[i] = make_float4(0.f, 0.f, 0.f, 0.f);
}

// ---------------- K-prep: fp16 weights ----------------------------------------
__global__ void prep_w(const float* __restrict__ Ws, const float* __restrict__ Wd,
                       const float* __restrict__ We)
{
    int idx = blockIdx.x * blockDim.x + threadIdx.x;
    if (idx >= 3 * FEAT * FEAT) return;
    int w = idx / (FEAT * FEAT);
    int i = idx - w * (FEAT * FEAT);
    const float* srcp = (w == 0) ? Ws : (w == 1) ? Wd : We;
    g_wh[w * FEAT * FEAT + i] = __float2half_rn(srcp[i]);
}

// ================= node kernel: both projections, single-term fp16 W ==========
__global__ __launch_bounds__(256, 2) void node_dual(
    const float* __restrict__ A,
    const __half* __restrict__ Wh1, const float* __restrict__ b1,
    __half* __restrict__ C1,
    const __half* __restrict__ Wh2, const float* __restrict__ b2,
    __half* __restrict__ C2)
{
    extern __shared__ char smem[];
    const u32 sbase = smem_u32(smem);
    float* sf = (float*)(smem + SD_N);
    const int tid = threadIdx.x;
    const int lane = tid & 31;
    const int wid = tid >> 5;
    const int warp_m = wid >> 1, warp_n = wid & 1;
    const int bm = blockIdx.x * 128;

    const int a_row = warp_m * 32 + ((lane >> 3) & 1) * 8 + (lane & 7);
    const int a_col = (lane >> 4) * 8;
    const u32 a_base = (u32)(a_row * PAD2 + a_col) * 2;
    const int b_row = warp_n * 64 + (lane >> 4) * 8 + (lane & 7);
    const int b_col = ((lane >> 3) & 1) * 8;
    const u32 b_base = (u32)(b_row * PAD2 + b_col) * 2;

    float acc[2][8][4];

    // load A (f32 -> fp16)
#pragma unroll
    for (int it = 0; it < 16; it++) {
        int idx = it * 256 + tid;
        int row = idx >> 5;
        int c4  = (idx & 31) << 2;
        float4 av = make_float4(0.f, 0.f, 0.f, 0.f);
        if (bm + row < N_NODES)
            av = *(const float4*)(A + (size_t)(bm + row) * FEAT + c4);
        *(u64*)(smem + SA_N + (u32)(row * PAD2 + c4) * 2) = cvt4_f16(av);
    }
    for (int pass = 0; pass < 2; pass++) {
        const __half* Wh = pass ? Wh2 : Wh1;
#pragma unroll
        for (int it = 0; it < 8; it++) {
            int idx = it * 256 + tid;
            int row = idx >> 4;
            int c8  = (idx & 15) << 3;
            cp_async16(sbase + SW_N + (u32)(row * PAD2 + c8) * 2,
                       Wh + (size_t)row * FEAT + c8);
        }
        cp_async_wait_all();
        __syncthreads();

#pragma unroll
        for (int mi = 0; mi < 2; mi++)
#pragma unroll
            for (int ng = 0; ng < 8; ng++)
#pragma unroll
                for (int j = 0; j < 4; j++) acc[mi][ng][j] = 0.0f;

#pragma unroll
        for (int ks = 0; ks < 8; ks++) {
            const u32 koff = (u32)ks * 32;
            u32 ah[2][4];
            ldsm4(ah[0][0], ah[0][1], ah[0][2], ah[0][3], sbase + SA_N + a_base + koff);
            ldsm4(ah[1][0], ah[1][1], ah[1][2], ah[1][3],
                  sbase + SA_N + a_base + (u32)(16 * PAD2) * 2 + koff);
#pragma unroll
            for (int p = 0; p < 4; p++) {
                const u32 poff = (u32)(p * 16 * PAD2) * 2 + koff;
                u32 bh[4];
                ldsm4(bh[0], bh[1], bh[2], bh[3], sbase + SW_N + b_base + poff);
                int g0 = 2 * p, g1 = 2 * p + 1;
                mma_f16(acc[0][g0], ah[0], bh[0], bh[1]);
                mma_f16(acc[1][g0], ah[1], bh[0], bh[1]);
                mma_f16(acc[0][g1], ah[0], bh[2], bh[3]);
                mma_f16(acc[1][g1], ah[1], bh[2], bh[3]);
            }
        }
        __syncthreads();
        // stage D (f32) over W region
#pragma unroll
        for (int mi = 0; mi < 2; mi++) {
            int r0 = warp_m * 32 + mi * 16 + (lane >> 2);
            int cc = warp_n * 64 + (lane & 3) * 2;
#pragma unroll
            for (int ng = 0; ng < 8; ng++) {
                int col = cc + ng * 8;
                *(float2*)&sf[r0 * 132 + col] =
                    make_float2(acc[mi][ng][0], acc[mi][ng][1]);
                *(float2*)&sf[(r0 + 8) * 132 + col] =
                    make_float2(acc[mi][ng][2], acc[mi][ng][3]);
            }
        }
        __syncthreads();
        // store as fp16 (+bias)
        {
            const float* bias = pass ? b2 : b1;
            __half* C = pass ? C2 : C1;
            float4 b4 = *(const float4*)(bias + (tid & 31) * 4);
#pragma unroll 4
            for (int i = 0; i < 16; i++) {
                int row = i * 8 + (tid >> 5);
                int gr = bm + row;
                if (gr < N_NODES) {
                    float4 v = *(const float4*)&sf[row * 132 + (tid & 31) * 4];
                    v.x += b4.x; v.y += b4.y; v.z += b4.z; v.w += b4.w;
                    u64 hv = cvt4_f16(v);
                    *(u64*)(C + (size_t)gr * FEAT + (tid & 31) * 4) = hv;
                }
            }
        }
        __syncthreads();
    }
}

// ====== edge kernel: persistent, 64-edge tiles, 256 thr, 4 CTA/SM ===========
// Warp tile 32x32 (2x4 warp grid). D (fp16) overlays the A region after MMA.
__global__ __launch_bounds__(256, 4) void edge_persist(
    const float* __restrict__ A,
    const __half* __restrict__ Wh,
    const int* __restrict__ src, const int* __restrict__ dst,
    const float* __restrict__ attn, float* __restrict__ out)
{
    extern __shared__ char smem[];
    const u32 sbase = smem_u32(smem);
    const int tid = threadIdx.x;
    const int lane = tid & 31;
    const int wid = tid >> 5;                      // 0..7
    const int warp_m = wid >> 2, warp_n = wid & 3; // 2x4 grid, 32x32 warp tiles

    // ---- W (fp16) loaded ONCE per CTA ----
#pragma unroll
    for (int it = 0; it < 8; it++) {
        int idx = it * 256 + tid;                  // 0..2047 uint4
        int row = idx >> 4;
        int c8  = (idx & 15) << 3;
        cp_async16(sbase + SW_E + (u32)(row * PAD2 + c8) * 2,
                   Wh + (size_t)row * FEAT + c8);
    }
    cp_async_wait_all();
    __syncthreads();

    const float4 at = *(const float4*)(attn + lane * 4);

    const int a_row = warp_m * 32 + ((lane >> 3) & 1) * 8 + (lane & 7);
    const int a_col = (lane >> 4) * 8;
    const u32 a_base = (u32)(a_row * PAD2 + a_col) * 2;
    const int b_row = warp_n * 32 + (lane >> 4) * 8 + (lane & 7);
    const int b_col = ((lane >> 3) & 1) * 8;
    const u32 b_base = (u32)(b_row * PAD2 + b_col) * 2;

    for (int t = blockIdx.x; t < NT2; t += GRID_P4) {
        __syncthreads();                           // BAR0: epi(t-1) done reading D

        // ---- load A(t): 64x128 f32 stream -> fp16 smem (overlay region) ----
#pragma unroll
        for (int it = 0; it < 8; it++) {
            int idx = it * 256 + tid;              // 0..2047 float4
            int row = idx >> 5;                    // 0..63
            int c4  = (idx & 31) << 2;
            float4 av = ldcs4(A + ((size_t)t * 64 + row) * FEAT + c4);
            *(u64*)(smem + SAD_E + (u32)(row * PAD2 + c4) * 2) = cvt4_f16(av);
        }
        int s_pre = 0, d_pre = 0;
        if (lane < 8) {
            s_pre = __ldg(src + t * 64 + wid * 8 + lane);
            d_pre = __ldg(dst + t * 64 + wid * 8 + lane);
        }
        __syncthreads();                           // BAR1: A ready

        // ---- MMA: warp tile 32x32 ----
        float acc[2][4][4];
#pragma unroll
        for (int mi = 0; mi < 2; mi++)
#pragma unroll
            for (int ng = 0; ng < 4; ng++)
#pragma unroll
                for (int j = 0; j < 4; j++) acc[mi][ng][j] = 0.0f;

#pragma unroll
        for (int ks = 0; ks < 8; ks++) {
            const u32 koff = (u32)ks * 32;
            u32 ah[2][4];
            ldsm4(ah[0][0], ah[0][1], ah[0][2], ah[0][3], sbase + SAD_E + a_base + koff);
            ldsm4(ah[1][0], ah[1][1], ah[1][2], ah[1][3],
                  sbase + SAD_E + a_base + (u32)(16 * PAD2) * 2 + koff);
#pragma unroll
            for (int p = 0; p < 2; p++) {
                const u32 poff = (u32)(p * 16 * PAD2) * 2 + koff;
                u32 bh[4];
                ldsm4(bh[0], bh[1], bh[2], bh[3], sbase + SW_E + b_base + poff);
                int g0 = 2 * p, g1 = 2 * p + 1;
                mma_f16(acc[0][g0], ah[0], bh[0], bh[1]);
                mma_f16(acc[1][g0], ah[1], bh[0], bh[1]);
                mma_f16(acc[0][g1], ah[0], bh[2], bh[3]);
                mma_f16(acc[1][g1], ah[1], bh[2], bh[3]);
            }
        }
        __syncthreads();                           // BAR2: all A reads retired

        // ---- stage D as fp16 over the A region ----
#pragma unroll
        for (int mi = 0; mi < 2; mi++) {
            int r0 = warp_m * 32 + mi * 16 + (lane >> 2);
            int cc = warp_n * 32 + (lane & 3) * 2;
#pragma unroll
            for (int ng = 0; ng < 4; ng++) {
                int col = cc + ng * 8;
                *(u32*)(smem + SAD_E + (u32)(r0 * PAD2 + col) * 2) =
                    cvt2_f16(acc[mi][ng][0], acc[mi][ng][1]);
                *(u32*)(smem + SAD_E + (u32)((r0 + 8) * PAD2 + col) * 2) =
                    cvt2_f16(acc[mi][ng][2], acc[mi][ng][3]);
            }
        }
        __syncthreads();                           // BAR3: D ready

        // ---- GATv2 epilogue: 8 edges per warp ----
#pragma unroll 4
        for (int e8 = 0; e8 < 8; e8++) {
            int el = wid * 8 + e8;
            int s = __shfl_sync(0xffffffffu, s_pre, e8);
            int d = __shfl_sync(0xffffffffu, d_pre, e8);

            uint2 fev = *(const uint2*)(smem + SAD_E + (u32)(el * PAD2 + lane * 4) * 2);
            float4 fe = h4_to_f4(fev);
            float4 fs = gather_h4(g_feat_src, s, lane);
            float4 fd = gather_h4(g_feat_dst, d, lane);

            float t0v = fs.x + fd.x + fe.x;
            float t1v = fs.y + fd.y + fe.y;
            float t2v = fs.z + fd.z + fe.z;
            float t3v = fs.w + fd.w + fe.w;
            float l0 = (t0v >= 0.f) ? t0v : NEG_SLOPE * t0v;
            float l1 = (t1v >= 0.f) ? t1v : NEG_SLOPE * t1v;
            float l2 = (t2v >= 0.f) ? t2v : NEG_SLOPE * t2v;
            float l3 = (t3v >= 0.f) ? t3v : NEG_SLOPE * t3v;

            float p = l0 * at.x + l1 * at.y + l2 * at.z + l3 * at.w;
            p += __shfl_xor_sync(0xffffffffu, p, 1);
            p += __shfl_xor_sync(0xffffffffu, p, 2);

            float ex = __expf(p);

            if ((lane & 3) == 0)
                atomicAdd(&g_z[(size_t)d * HEADS + (lane >> 2)], ex);

            float mx = (fs.x + fe.x) * ex;
            float my = (fs.y + fe.y) * ex;
            float mz = (fs.z + fe.z) * ex;
            float mw = (fs.w + fe.w) * ex;

            float* op = out + (size_t)d * FEAT + lane * 4;
            asm volatile("red.global.add.v4.f32 [%0], {%1,%2,%3,%4};"
                         :: "l"(op), "f"(mx), "f"(my), "f"(mz), "f"(mw)
                         : "memory");
        }
    }
}

// ---------------- finalize out = relu(acc / z) --------------------------------
__global__ void finalize(float* __restrict__ out)
{
    int i = blockIdx.x * blockDim.x + threadIdx.x;
    if (i >= N_NODES * 32) return;
    int n = i >> 5;
    int q = i & 31;
    int h = q >> 2;
    float z = g_z[(size_t)n * HEADS + h];
    float inv = (z > 0.f) ? (1.f / z) : 0.f;
    float4 v = *(float4*)(out + (size_t)n * FEAT + q * 4);
    v.x = fmaxf(v.x * inv, 0.f);
    v.y = fmaxf(v.y * inv, 0.f);
    v.z = fmaxf(v.z * inv, 0.f);
    v.w = fmaxf(v.w * inv, 0.f);
    *(float4*)(out + (size_t)n * FEAT + q * 4) = v;
}

// ---------------- launch -----------------------------------------------------
extern "C" void kernel_launch(void* const* d_in, const int* in_sizes, int n_in,
                              void* d_out, int out_size)
{
    const float* x      = (const float*)d_in[0];
    const float* efeat  = (const float*)d_in[1];
    const int*   src    = (const int*)d_in[2];
    const int*   dst    = (const int*)d_in[3];
    const float* W_src  = (const float*)d_in[4];
    const float* b_src  = (const float*)d_in[5];
    const float* W_dst  = (const float*)d_in[6];
    const float* b_dst  = (const float*)d_in[7];
    const float* W_edge = (const float*)d_in[8];
    const float* attn   = (const float*)d_in[9];
    float* out = (float*)d_out;

    __half *p_fsrc = nullptr, *p_fdst = nullptr, *p_w = nullptr;
    cudaGetSymbolAddress((void**)&p_fsrc, g_feat_src);
    cudaGetSymbolAddress((void**)&p_fdst, g_feat_dst);
    cudaGetSymbolAddress((void**)&p_w, g_wh);

    cudaFuncSetAttribute(node_dual,
                         cudaFuncAttributeMaxDynamicSharedMemorySize, SMEM_N);
    cudaFuncSetAttribute(edge_persist,
                         cudaFuncAttributeMaxDynamicSharedMemorySize, SMEM_E);

    zero_kernel<<<(N_NODES * 32 + 255) / 256, 256>>>((float4*)out);
    prep_w<<<(3 * FEAT * FEAT + 255) / 256, 256>>>(W_src, W_dst, W_edge);

    const int WSZ = FEAT * FEAT;
    int nb_node = (N_NODES + 127) / 128;   // 391
    node_dual<<<nb_node, 256, SMEM_N>>>(
        x, p_w + 0 * WSZ, b_src, p_fsrc,
           p_w + 1 * WSZ, b_dst, p_fdst);

    edge_persist<<<GRID_P4, 256, SMEM_E>>>(
        efeat, p_w + 2 * WSZ, src, dst, attn, out);

    finalize<<<(N_NODES * 32 + 255) / 256, 256>>>(out);
}

// round 15
// speedup vs baseline: 1.0891x; 1.0891x over previous
#include <cuda_runtime.h>
#include <cuda_fp16.h>
#include <cstdint>
#include <cstddef>

#define N_NODES 50000
#define N_EDGES 800000
#define FEAT    128
#define HEADS   8
#define NEG_SLOPE 0.2f
#define NT2     12500       // 64-edge tiles
#define GRID_P3 444         // persistent CTAs (3 per SM)

typedef unsigned long long u64;
typedef unsigned int u32;

// ---------------- device scratch ---------------------------------------------
__device__ __half g_feat_src[(size_t)N_NODES * FEAT];   // 12.8 MB (fp16)
__device__ __half g_feat_dst[(size_t)N_NODES * FEAT];   // 12.8 MB (fp16)
__device__ float g_z[(size_t)N_NODES * HEADS];
__device__ __half g_wh[3 * FEAT * FEAT];                // fp16 weights

// ---------------- smem maps ---------------------------------------------------
#define PAD2    136
// node kernel (256 thr, 2 CTA/SM): A tile + W tile + f32 D overlay on W
#define SA_N    0
#define SW_N    34816
#define SD_N    34816
#define SMEM_N  104448
// edge kernel (256 thr, 3 CTA/SM): A/D overlay (64 x 136 fp16) + W fp16
#define SAD_E   0               // A during MMA, then D (fp16) after
#define SW_E    17408           // 128 x 136 fp16 = 34816
#define SMEM_E  52224

// ---------------- helpers -----------------------------------------------------
__device__ __forceinline__ u32 smem_u32(const void* p) {
    u32 a;
    asm("{ .reg .u64 t; cvta.to.shared.u64 t, %1; cvt.u32.u64 %0, t; }"
        : "=r"(a) : "l"(p));
    return a;
}
__device__ __forceinline__ void ldsm4(u32& r0, u32& r1, u32& r2, u32& r3, u32 addr) {
    asm volatile("ldmatrix.sync.aligned.m8n8.x4.shared.b16 {%0,%1,%2,%3}, [%4];"
                 : "=r"(r0), "=r"(r1), "=r"(r2), "=r"(r3) : "r"(addr));
}
__device__ __forceinline__ void mma_f16(float* c, const u32* a, u32 b0, u32 b1) {
    asm volatile("mma.sync.aligned.m16n8k16.row.col.f32.f16.f16.f32 "
                 "{%0,%1,%2,%3}, {%4,%5,%6,%7}, {%8,%9}, {%0,%1,%2,%3};"
                 : "+f"(c[0]), "+f"(c[1]), "+f"(c[2]), "+f"(c[3])
                 : "r"(a[0]), "r"(a[1]), "r"(a[2]), "r"(a[3]), "r"(b0), "r"(b1));
}
__device__ __forceinline__ u64 cvt4_f16(float4 v) {
    u32 p01, p23;
    asm("cvt.rn.f16x2.f32 %0, %1, %2;" : "=r"(p01) : "f"(v.y), "f"(v.x));
    asm("cvt.rn.f16x2.f32 %0, %1, %2;" : "=r"(p23) : "f"(v.w), "f"(v.z));
    return (u64)p01 | ((u64)p23 << 32);
}
__device__ __forceinline__ u32 cvt2_f16(float a, float b) {
    u32 r;
    asm("cvt.rn.f16x2.f32 %0, %1, %2;" : "=r"(r) : "f"(b), "f"(a));
    return r;
}
__device__ __forceinline__ void cp_async16(u32 saddr, const void* gaddr) {
    asm volatile("cp.async.cg.shared.global [%0], [%1], 16;"
                 :: "r"(saddr), "l"(gaddr) : "memory");
}
__device__ __forceinline__ void cp_async_wait_all() {
    asm volatile("cp.async.commit_group;" ::: "memory");
    asm volatile("cp.async.wait_group 0;" ::: "memory");
}
__device__ __forceinline__ float4 h4_to_f4(uint2 hv) {
    __half2 h01 = *reinterpret_cast<__half2*>(&hv.x);
    __half2 h23 = *reinterpret_cast<__half2*>(&hv.y);
    float2 f01 = __half22float2(h01);
    float2 f23 = __half22float2(h23);
    return make_float4(f01.x, f01.y, f23.x, f23.y);
}
__device__ __forceinline__ float4 gather_h4(const __half* base, int node, int lane) {
    uint2 hv = *(const uint2*)(base + (size_t)node * FEAT + lane * 4);
    return h4_to_f4(hv);
}
__device__ __forceinline__ float4 ldcs4(const float* p) {
    float4 v;
    asm("ld.global.cs.v4.f32 {%0,%1,%2,%3}, [%4];"
        : "=f"(v.x), "=f"(v.y), "=f"(v.z), "=f"(v.w) : "l"(p));
    return v;
}

// ---------------- K0: zero ----------------------------------------------------
__global__ void zero_kernel(float4* __restrict__ out4)
{
    int i = blockIdx.x * blockDim.x + threadIdx.x;
    if (i < N_NODES * 32) out4[i] = make_float4(0.f, 0.f, 0.f, 0.f);
    if (i < N_NODES * HEADS / 4) ((float4*)g_z)[i] = make_float4(0.f, 0.f, 0.f, 0.f);
}

// ---------------- K-prep: fp16 weights ----------------------------------------
__global__ void prep_w(const float* __restrict__ Ws, const float* __restrict__ Wd,
                       const float* __restrict__ We)
{
    int idx = blockIdx.x * blockDim.x + threadIdx.x;
    if (idx >= 3 * FEAT * FEAT) return;
    int w = idx / (FEAT * FEAT);
    int i = idx - w * (FEAT * FEAT);
    const float* srcp = (w == 0) ? Ws : (w == 1) ? Wd : We;
    g_wh[w * FEAT * FEAT + i] = __float2half_rn(srcp[i]);
}

// ================= node kernel: both projections, single-term fp16 W ==========
__global__ __launch_bounds__(256, 2) void node_dual(
    const float* __restrict__ A,
    const __half* __restrict__ Wh1, const float* __restrict__ b1,
    __half* __restrict__ C1,
    const __half* __restrict__ Wh2, const float* __restrict__ b2,
    __half* __restrict__ C2)
{
    extern __shared__ char smem[];
    const u32 sbase = smem_u32(smem);
    float* sf = (float*)(smem + SD_N);
    const int tid = threadIdx.x;
    const int lane = tid & 31;
    const int wid = tid >> 5;
    const int warp_m = wid >> 1, warp_n = wid & 1;
    const int bm = blockIdx.x * 128;

    const int a_row = warp_m * 32 + ((lane >> 3) & 1) * 8 + (lane & 7);
    const int a_col = (lane >> 4) * 8;
    const u32 a_base = (u32)(a_row * PAD2 + a_col) * 2;
    const int b_row = warp_n * 64 + (lane >> 4) * 8 + (lane & 7);
    const int b_col = ((lane >> 3) & 1) * 8;
    const u32 b_base = (u32)(b_row * PAD2 + b_col) * 2;

    float acc[2][8][4];

    // load A (f32 -> fp16)
#pragma unroll
    for (int it = 0; it < 16; it++) {
        int idx = it * 256 + tid;
        int row = idx >> 5;
        int c4  = (idx & 31) << 2;
        float4 av = make_float4(0.f, 0.f, 0.f, 0.f);
        if (bm + row < N_NODES)
            av = *(const float4*)(A + (size_t)(bm + row) * FEAT + c4);
        *(u64*)(smem + SA_N + (u32)(row * PAD2 + c4) * 2) = cvt4_f16(av);
    }
    for (int pass = 0; pass < 2; pass++) {
        const __half* Wh = pass ? Wh2 : Wh1;
#pragma unroll
        for (int it = 0; it < 8; it++) {
            int idx = it * 256 + tid;
            int row = idx >> 4;
            int c8  = (idx & 15) << 3;
            cp_async16(sbase + SW_N + (u32)(row * PAD2 + c8) * 2,
                       Wh + (size_t)row * FEAT + c8);
        }
        cp_async_wait_all();
        __syncthreads();

#pragma unroll
        for (int mi = 0; mi < 2; mi++)
#pragma unroll
            for (int ng = 0; ng < 8; ng++)
#pragma unroll
                for (int j = 0; j < 4; j++) acc[mi][ng][j] = 0.0f;

#pragma unroll
        for (int ks = 0; ks < 8; ks++) {
            const u32 koff = (u32)ks * 32;
            u32 ah[2][4];
            ldsm4(ah[0][0], ah[0][1], ah[0][2], ah[0][3], sbase + SA_N + a_base + koff);
            ldsm4(ah[1][0], ah[1][1], ah[1][2], ah[1][3],
                  sbase + SA_N + a_base + (u32)(16 * PAD2) * 2 + koff);
#pragma unroll
            for (int p = 0; p < 4; p++) {
                const u32 poff = (u32)(p * 16 * PAD2) * 2 + koff;
                u32 bh[4];
                ldsm4(bh[0], bh[1], bh[2], bh[3], sbase + SW_N + b_base + poff);
                int g0 = 2 * p, g1 = 2 * p + 1;
                mma_f16(acc[0][g0], ah[0], bh[0], bh[1]);
                mma_f16(acc[1][g0], ah[1], bh[0], bh[1]);
                mma_f16(acc[0][g1], ah[0], bh[2], bh[3]);
                mma_f16(acc[1][g1], ah[1], bh[2], bh[3]);
            }
        }
        __syncthreads();
        // stage D (f32) over W region
#pragma unroll
        for (int mi = 0; mi < 2; mi++) {
            int r0 = warp_m * 32 + mi * 16 + (lane >> 2);
            int cc = warp_n * 64 + (lane & 3) * 2;
#pragma unroll
            for (int ng = 0; ng < 8; ng++) {
                int col = cc + ng * 8;
                *(float2*)&sf[r0 * 132 + col] =
                    make_float2(acc[mi][ng][0], acc[mi][ng][1]);
                *(float2*)&sf[(r0 + 8) * 132 + col] =
                    make_float2(acc[mi][ng][2], acc[mi][ng][3]);
            }
        }
        __syncthreads();
        // store as fp16 (+bias)
        {
            const float* bias = pass ? b2 : b1;
            __half* C = pass ? C2 : C1;
            float4 b4 = *(const float4*)(bias + (tid & 31) * 4);
#pragma unroll 4
            for (int i = 0; i < 16; i++) {
                int row = i * 8 + (tid >> 5);
                int gr = bm + row;
                if (gr < N_NODES) {
                    float4 v = *(const float4*)&sf[row * 132 + (tid & 31) * 4];
                    v.x += b4.x; v.y += b4.y; v.z += b4.z; v.w += b4.w;
                    u64 hv = cvt4_f16(v);
                    *(u64*)(C + (size_t)gr * FEAT + (tid & 31) * 4) = hv;
                }
            }
        }
        __syncthreads();
    }
}

// ====== edge kernel: persistent, 64-edge tiles, 256 thr, 3 CTA/SM ===========
// Warp tile 32x32 (2x4 warp grid). D (fp16) overlays the A region after MMA.
// (round-13 configuration — measured best: 201 us, 80 regs)
__global__ __launch_bounds__(256, 3) void edge_persist(
    const float* __restrict__ A,
    const __half* __restrict__ Wh,
    const int* __restrict__ src, const int* __restrict__ dst,
    const float* __restrict__ attn, float* __restrict__ out)
{
    extern __shared__ char smem[];
    const u32 sbase = smem_u32(smem);
    const int tid = threadIdx.x;
    const int lane = tid & 31;
    const int wid = tid >> 5;                      // 0..7
    const int warp_m = wid >> 2, warp_n = wid & 3; // 2x4 grid, 32x32 warp tiles

    // ---- W (fp16) loaded ONCE per CTA ----
#pragma unroll
    for (int it = 0; it < 8; it++) {
        int idx = it * 256 + tid;                  // 0..2047 uint4
        int row = idx >> 4;
        int c8  = (idx & 15) << 3;
        cp_async16(sbase + SW_E + (u32)(row * PAD2 + c8) * 2,
                   Wh + (size_t)row * FEAT + c8);
    }
    cp_async_wait_all();
    __syncthreads();

    const float4 at = *(const float4*)(attn + lane * 4);

    const int a_row = warp_m * 32 + ((lane >> 3) & 1) * 8 + (lane & 7);
    const int a_col = (lane >> 4) * 8;
    const u32 a_base = (u32)(a_row * PAD2 + a_col) * 2;
    const int b_row = warp_n * 32 + (lane >> 4) * 8 + (lane & 7);
    const int b_col = ((lane >> 3) & 1) * 8;
    const u32 b_base = (u32)(b_row * PAD2 + b_col) * 2;

    for (int t = blockIdx.x; t < NT2; t += GRID_P3) {
        __syncthreads();                           // BAR0: epi(t-1) done reading D

        // ---- load A(t): 64x128 f32 stream -> fp16 smem (overlay region) ----
#pragma unroll
        for (int it = 0; it < 8; it++) {
            int idx = it * 256 + tid;              // 0..2047 float4
            int row = idx >> 5;                    // 0..63
            int c4  = (idx & 31) << 2;
            float4 av = ldcs4(A + ((size_t)t * 64 + row) * FEAT + c4);
            *(u64*)(smem + SAD_E + (u32)(row * PAD2 + c4) * 2) = cvt4_f16(av);
        }
        int s_pre = 0, d_pre = 0;
        if (lane < 8) {
            s_pre = __ldg(src + t * 64 + wid * 8 + lane);
            d_pre = __ldg(dst + t * 64 + wid * 8 + lane);
        }
        __syncthreads();                           // BAR1: A ready

        // ---- MMA: warp tile 32x32 ----
        float acc[2][4][4];
#pragma unroll
        for (int mi = 0; mi < 2; mi++)
#pragma unroll
            for (int ng = 0; ng < 4; ng++)
#pragma unroll
                for (int j = 0; j < 4; j++) acc[mi][ng][j] = 0.0f;

#pragma unroll
        for (int ks = 0; ks < 8; ks++) {
            const u32 koff = (u32)ks * 32;
            u32 ah[2][4];
            ldsm4(ah[0][0], ah[0][1], ah[0][2], ah[0][3], sbase + SAD_E + a_base + koff);
            ldsm4(ah[1][0], ah[1][1], ah[1][2], ah[1][3],
                  sbase + SAD_E + a_base + (u32)(16 * PAD2) * 2 + koff);
#pragma unroll
            for (int p = 0; p < 2; p++) {
                const u32 poff = (u32)(p * 16 * PAD2) * 2 + koff;
                u32 bh[4];
                ldsm4(bh[0], bh[1], bh[2], bh[3], sbase + SW_E + b_base + poff);
                int g0 = 2 * p, g1 = 2 * p + 1;
                mma_f16(acc[0][g0], ah[0], bh[0], bh[1]);
                mma_f16(acc[1][g0], ah[1], bh[0], bh[1]);
                mma_f16(acc[0][g1], ah[0], bh[2], bh[3]);
                mma_f16(acc[1][g1], ah[1], bh[2], bh[3]);
            }
        }
        __syncthreads();                           // BAR2: all A reads retired

        // ---- stage D as fp16 over the A region ----
#pragma unroll
        for (int mi = 0; mi < 2; mi++) {
            int r0 = warp_m * 32 + mi * 16 + (lane >> 2);
            int cc = warp_n * 32 + (lane & 3) * 2;
#pragma unroll
            for (int ng = 0; ng < 4; ng++) {
                int col = cc + ng * 8;
                *(u32*)(smem + SAD_E + (u32)(r0 * PAD2 + col) * 2) =
                    cvt2_f16(acc[mi][ng][0], acc[mi][ng][1]);
                *(u32*)(smem + SAD_E + (u32)((r0 + 8) * PAD2 + col) * 2) =
                    cvt2_f16(acc[mi][ng][2], acc[mi][ng][3]);
            }
        }
        __syncthreads();                           // BAR3: D ready

        // ---- GATv2 epilogue: 8 edges per warp ----
#pragma unroll 4
        for (int e8 = 0; e8 < 8; e8++) {
            int el = wid * 8 + e8;
            int s = __shfl_sync(0xffffffffu, s_pre, e8);
            int d = __shfl_sync(0xffffffffu, d_pre, e8);

            uint2 fev = *(const uint2*)(smem + SAD_E + (u32)(el * PAD2 + lane * 4) * 2);
            float4 fe = h4_to_f4(fev);
            float4 fs = gather_h4(g_feat_src, s, lane);
            float4 fd = gather_h4(g_feat_dst, d, lane);

            float t0v = fs.x + fd.x + fe.x;
            float t1v = fs.y + fd.y + fe.y;
            float t2v = fs.z + fd.z + fe.z;
            float t3v = fs.w + fd.w + fe.w;
            float l0 = (t0v >= 0.f) ? t0v : NEG_SLOPE * t0v;
            float l1 = (t1v >= 0.f) ? t1v : NEG_SLOPE * t1v;
            float l2 = (t2v >= 0.f) ? t2v : NEG_SLOPE * t2v;
            float l3 = (t3v >= 0.f) ? t3v : NEG_SLOPE * t3v;

            float p = l0 * at.x + l1 * at.y + l2 * at.z + l3 * at.w;
            p += __shfl_xor_sync(0xffffffffu, p, 1);
            p += __shfl_xor_sync(0xffffffffu, p, 2);

            float ex = __expf(p);

            if ((lane & 3) == 0)
                atomicAdd(&g_z[(size_t)d * HEADS + (lane >> 2)], ex);

            float mx = (fs.x + fe.x) * ex;
            float my = (fs.y + fe.y) * ex;
            float mz = (fs.z + fe.z) * ex;
            float mw = (fs.w + fe.w) * ex;

            float* op = out + (size_t)d * FEAT + lane * 4;
            asm volatile("red.global.add.v4.f32 [%0], {%1,%2,%3,%4};"
                         :: "l"(op), "f"(mx), "f"(my), "f"(mz), "f"(mw)
                         : "memory");
        }
    }
}

// ---------------- finalize out = relu(acc / z) --------------------------------
__global__ void finalize(float* __restrict__ out)
{
    int i = blockIdx.x * blockDim.x + threadIdx.x;
    if (i >= N_NODES * 32) return;
    int n = i >> 5;
    int q = i & 31;
    int h = q >> 2;
    float z = g_z[(size_t)n * HEADS + h];
    float inv = (z > 0.f) ? (1.f / z) : 0.f;
    float4 v = *(float4*)(out + (size_t)n * FEAT + q * 4);
    v.x = fmaxf(v.x * inv, 0.f);
    v.y = fmaxf(v.y * inv, 0.f);
    v.z = fmaxf(v.z * inv, 0.f);
    v.w = fmaxf(v.w * inv, 0.f);
    *(float4*)(out + (size_t)n * FEAT + q * 4) = v;
}

// ---------------- launch -----------------------------------------------------
extern "C" void kernel_launch(void* const* d_in, const int* in_sizes, int n_in,
                              void* d_out, int out_size)
{
    const float* x      = (const float*)d_in[0];
    const float* efeat  = (const float*)d_in[1];
    const int*   src    = (const int*)d_in[2];
    const int*   dst    = (const int*)d_in[3];
    const float* W_src  = (const float*)d_in[4];
    const float* b_src  = (const float*)d_in[5];
    const float* W_dst  = (const float*)d_in[6];
    const float* b_dst  = (const float*)d_in[7];
    const float* W_edge = (const float*)d_in[8];
    const float* attn   = (const float*)d_in[9];
    float* out = (float*)d_out;

    __half *p_fsrc = nullptr, *p_fdst = nullptr, *p_w = nullptr;
    cudaGetSymbolAddress((void**)&p_fsrc, g_feat_src);
    cudaGetSymbolAddress((void**)&p_fdst, g_feat_dst);
    cudaGetSymbolAddress((void**)&p_w, g_wh);

    cudaFuncSetAttribute(node_dual,
                         cudaFuncAttributeMaxDynamicSharedMemorySize, SMEM_N);
    cudaFuncSetAttribute(edge_persist,
                         cudaFuncAttributeMaxDynamicSharedMemorySize, SMEM_E);

    zero_kernel<<<(N_NODES * 32 + 255) / 256, 256>>>((float4*)out);
    prep_w<<<(3 * FEAT * FEAT + 255) / 256, 256>>>(W_src, W_dst, W_edge);

    const int WSZ = FEAT * FEAT;
    int nb_node = (N_NODES + 127) / 128;   // 391
    node_dual<<<nb_node, 256, SMEM_N>>>(
        x, p_w + 0 * WSZ, b_src, p_fsrc,
           p_w + 1 * WSZ, b_dst, p_fdst);

    edge_persist<<<GRID_P3, 256, SMEM_E>>>(
        efeat, p_w + 2 * WSZ, src, dst, attn, out);

    finalize<<<(N_NODES * 32 + 255) / 256, 256>>>(out);
}